// round 6
// baseline (speedup 1.0000x reference)
#include <cuda_runtime.h>
#include <cstdint>

// ---------------------------------------------------------------------------
// OnlyLinear chain: y = L8(...L0(x)...), all affine -> fold into ONE GEMM.
//   Fold (tiny kernel):  E = W8*W7*...*W0   (10 x 784),  c = folded biases (10)
//   Main (big kernel):   Y[65536,10] = X[65536,784] * E^T + c
// Main kernel is HBM-bound (205 MB of X). Compute uses fma.rn.f32x2 (FFMA2)
// packing K in pairs; X staged via swizzled SMEM so E loads are broadcasts.
// ---------------------------------------------------------------------------

__device__ float g_Epack[392 * 10 * 2];  // [kk][o][2] : (E[2kk][o], E[2kk+1][o])
__device__ float g_c[10];

struct FoldArgs {
    const float* W[9];
    const float* b[9];
};

// Single-block fold: top-down accumulation keeps left factor at 10 rows.
// Total ~572K MACs. E intermediate never wider than 10x69 until final stage.
__global__ void fold_kernel(FoldArgs a) {
    __shared__ float E[2][10][72];
    __shared__ float cv[2][10];
    const int tid = threadIdx.x;

    // init with layer 8: E = W8 (10x10), c = b8
    if (tid < 100) E[0][tid / 10][tid % 10] = a.W[8][tid];
    if (tid < 10)  cv[0][tid] = a.b[8][tid];
    __syncthreads();

    const int dims[10] = {784, 69, 31, 10, 10, 10, 10, 10, 10, 10};
    int cur = 0;
    for (int i = 7; i >= 1; --i) {
        const int nin = dims[i], nout = dims[i + 1];
        const float* W = a.W[i];
        for (int idx = tid; idx < 10 * nin; idx += blockDim.x) {
            const int r = idx / nin;
            const int j = idx - r * nin;
            float s = 0.f;
            for (int k = 0; k < nout; ++k)
                s += E[cur][r][k] * W[k * nin + j];
            E[cur ^ 1][r][j] = s;
        }
        if (tid < 10) {
            float s = cv[cur][tid];
            const float* bv = a.b[i];
            for (int k = 0; k < nout; ++k)
                s += E[cur][tid][k] * bv[k];
            cv[cur ^ 1][tid] = s;
        }
        __syncthreads();
        cur ^= 1;
    }

    // final stage i=0: E(10x69) * W0(69x784) -> write packed to global
    const float* W0 = a.W[0];
    for (int idx = tid; idx < 7840; idx += blockDim.x) {
        const int r = idx / 784;
        const int j = idx - r * 784;
        float s = 0.f;
        #pragma unroll 23
        for (int k = 0; k < 69; ++k)
            s += E[cur][r][k] * W0[k * 784 + j];
        g_Epack[((j >> 1) * 10 + r) * 2 + (j & 1)] = s;
    }
    if (tid < 10) {
        float s = cv[cur][tid];
        const float* b0 = a.b[0];
        for (int k = 0; k < 69; ++k)
            s += E[cur][tid][k] * b0[k];
        g_c[tid] = s;
    }
}

// packed fp32x2 FMA: d.lo += a.lo*b.lo ; d.hi += a.hi*b.hi  (sm_10x FFMA2)
__device__ __forceinline__ void fma2(uint64_t& d, uint64_t a, uint64_t b) {
    asm("fma.rn.f32x2 %0, %1, %2, %0;" : "+l"(d) : "l"(a), "l"(b));
}

// Main GEMM: block = 64 threads (2 warps), 128 rows/block, grid = 512.
// K tiled in 14 tiles of 56. Each lane owns 2 rows (r, r+32), 10 outputs,
// accumulating in f32x2 pairs over (even k, odd k).
#define ROWS_PB 128
#define KT      56
#define NT      14

__global__ void __launch_bounds__(64) gemm_kernel(const float* __restrict__ X,
                                                  float* __restrict__ Y) {
    // Xs: 128 rows x 256B, element (row, kk) at granule (kk ^ (row&31))*8B
    __shared__ float Xs[ROWS_PB * 64];        // 32 KB
    __shared__ float Ep[28 * 10 * 2];         // 2.24 KB, [kk_local][o][2]

    const int tid  = threadIdx.x;
    const int lane = tid & 31;
    const int warp = tid >> 5;
    const int rowBlock = blockIdx.x * ROWS_PB;
    const int lr0 = warp * 64 + lane;         // local rows owned by this lane
    const int lr1 = lr0 + 32;

    uint64_t acc0[10], acc1[10];
    #pragma unroll
    for (int o = 0; o < 10; ++o) { acc0[o] = 0ull; acc1[o] = 0ull; }

    const float4* src = (const float4*)X;     // X row pitch = 196 float4

    for (int t = 0; t < NT; ++t) {
        __syncthreads();  // previous tile's compute done before overwrite

        // stage E tile (560 floats; L2-hot, shared by all 512 blocks)
        for (int i = tid; i < 560; i += 64)
            Ep[i] = g_Epack[t * 560 + i];

        // stage X tile: 128 rows x 14 float4, swizzled 8B-granule store
        for (int i = tid; i < ROWS_PB * 14; i += 64) {
            const int r = i / 14;
            const int c = i - r * 14;
            float4 v = src[(rowBlock + r) * 196 + t * 14 + c];
            char* base = (char*)Xs + r * 256;
            const int g0 = (2 * c)     ^ (r & 31);
            const int g1 = (2 * c + 1) ^ (r & 31);
            *(float2*)(base + g0 * 8) = make_float2(v.x, v.y);
            *(float2*)(base + g1 * 8) = make_float2(v.z, v.w);
        }
        __syncthreads();

        const char* b0 = (const char*)Xs + lr0 * 256;
        const char* b1 = (const char*)Xs + lr1 * 256;

        #pragma unroll 4
        for (int kk = 0; kk < 28; ++kk) {
            const int off = (kk ^ lane) << 3;           // conflict-free LDS.64
            uint64_t x0 = *(const uint64_t*)(b0 + off); // (X[r0][2k],X[r0][2k+1])
            uint64_t x1 = *(const uint64_t*)(b1 + off);
            const ulonglong2* ep = (const ulonglong2*)&Ep[kk * 20];
            #pragma unroll
            for (int oo = 0; oo < 5; ++oo) {            // LDS.128 broadcast: 2 outputs
                ulonglong2 e = ep[oo];
                fma2(acc0[2 * oo],     x0, e.x);
                fma2(acc1[2 * oo],     x1, e.x);
                fma2(acc0[2 * oo + 1], x0, e.y);
                fma2(acc1[2 * oo + 1], x1, e.y);
            }
        }
    }

    // epilogue: reduce even/odd halves, add bias, store
    const int gr0 = rowBlock + lr0;
    const int gr1 = rowBlock + lr1;
    #pragma unroll
    for (int o = 0; o < 10; ++o) {
        float l0, h0, l1, h1;
        asm("mov.b64 {%0,%1}, %2;" : "=f"(l0), "=f"(h0) : "l"(acc0[o]));
        asm("mov.b64 {%0,%1}, %2;" : "=f"(l1), "=f"(h1) : "l"(acc1[o]));
        const float bias = g_c[o];
        Y[gr0 * 10 + o] = l0 + h0 + bias;
        Y[gr1 * 10 + o] = l1 + h1 + bias;
    }
}

extern "C" void kernel_launch(void* const* d_in, const int* in_sizes, int n_in,
                              void* d_out, int out_size) {
    (void)in_sizes; (void)n_in; (void)out_size;
    FoldArgs fa;
    for (int i = 0; i < 9; ++i) {
        fa.W[i] = (const float*)d_in[1 + 2 * i];
        fa.b[i] = (const float*)d_in[2 + 2 * i];
    }
    fold_kernel<<<1, 1024>>>(fa);
    gemm_kernel<<<512, 64>>>((const float*)d_in[0], (float*)d_out);
}

// round 7
// speedup vs baseline: 1.4258x; 1.4258x over previous
#include <cuda_runtime.h>
#include <cstdint>

// ---------------------------------------------------------------------------
// OnlyLinear chain: fold 9 affine layers into one E[10,784], c[10], then
//   Y[65536,10] = X[65536,784] * E^T + c
// R6: (a) parallel fold (49 blocks, redundant tiny chain, coalesced W0 pass)
//     (b) gemm: 1 row/lane (2048 warps, 2x occupancy), register+smem
//         double-buffered pipeline with one __syncthreads per K-tile.
// ---------------------------------------------------------------------------

__device__ float g_Epack[392 * 10 * 2];  // [kk][o][2] : (E[2kk][o], E[2kk+1][o])
__device__ float g_c[10];

struct FoldArgs {
    const float* W[9];
    const float* b[9];
};

// 49 blocks x 256 threads. Each block redundantly folds W8..W1 into a 10x69
// matrix in smem (~30K MACs, weights L2-hot), then computes its 16 columns of
// the final 10x784 = E(10x69) * W0(69x784) with coalesced W0 reads.
__global__ void fold_kernel(FoldArgs a) {
    __shared__ float E[2][10][72];
    __shared__ float cv[2][10];
    const int tid = threadIdx.x;

    if (tid < 100) E[0][tid / 10][tid % 10] = a.W[8][tid];
    if (tid < 10)  cv[0][tid] = a.b[8][tid];
    __syncthreads();

    const int dims[10] = {784, 69, 31, 10, 10, 10, 10, 10, 10, 10};
    int cur = 0;
    for (int i = 7; i >= 1; --i) {
        const int nin = dims[i], nout = dims[i + 1];
        const float* W = a.W[i];
        for (int idx = tid; idx < 10 * nin; idx += blockDim.x) {
            const int r = idx / nin;
            const int j = idx - r * nin;
            float s = 0.f;
            for (int k = 0; k < nout; ++k)
                s += E[cur][r][k] * W[k * nin + j];
            E[cur ^ 1][r][j] = s;
        }
        if (tid < 10) {
            float s = cv[cur][tid];
            const float* bv = a.b[i];
            for (int k = 0; k < nout; ++k)
                s += E[cur][tid][k] * bv[k];
            cv[cur ^ 1][tid] = s;
        }
        __syncthreads();
        cur ^= 1;
    }

    // final stage: this block owns columns [j0, j0+16) of 784
    const float* W0 = a.W[0];
    const int j0 = blockIdx.x * 16;
    if (tid < 160) {
        const int r = tid >> 4;
        const int j = j0 + (tid & 15);
        float s = 0.f;
        #pragma unroll 23
        for (int k = 0; k < 69; ++k)
            s += E[cur][r][k] * W0[k * 784 + j];
        g_Epack[((j >> 1) * 10 + r) * 2 + (j & 1)] = s;
    }
    if (blockIdx.x == 0 && tid < 10) {
        float s = cv[cur][tid];
        const float* b0 = a.b[0];
        for (int k = 0; k < 69; ++k)
            s += E[cur][tid][k] * b0[k];
        g_c[tid] = s;
    }
}

// packed fp32x2 FMA: d.lo += a.lo*b.lo ; d.hi += a.hi*b.hi  (sm_10x FFMA2)
__device__ __forceinline__ void fma2(uint64_t& d, uint64_t a, uint64_t b) {
    asm("fma.rn.f32x2 %0, %1, %2, %0;" : "+l"(d) : "l"(a), "l"(b));
}

// GEMM: block = 128 threads (4 warps), 128 rows/block (1 row per lane),
// grid = 512 -> 2048 warps. K split in 28 tiles of 28 (14 k-pairs).
// Per tile: X 128 rows x 112B staged via 8B-granule XOR-16 swizzle into a
// 128B-pitch smem row; E tile 280 floats. Both double-buffered; the next
// tile's global loads are issued into registers during current compute.
#define ROWS_PB 128
#define NT      28

__global__ void __launch_bounds__(128) gemm_kernel(const float* __restrict__ X,
                                                   float* __restrict__ Y) {
    __shared__ __align__(16) float Xs[2][ROWS_PB * 32];  // 2 x 16 KB
    __shared__ __align__(16) float Es[2][280];           // 2 x 1.1 KB

    const int tid = threadIdx.x;
    const int rowBlock = blockIdx.x * ROWS_PB;
    const float4* src = (const float4*)X;                // X pitch = 196 f4

    // staging geometry (constant across tiles): 896 f4 per tile, 7 per thread
    const float4* gp_[7];
    int sa_[7];
    #pragma unroll
    for (int j = 0; j < 7; ++j) {
        const int idx = j * 128 + tid;
        const int r = idx / 7;
        const int c = idx - r * 7;
        gp_[j] = src + (rowBlock + r) * 196 + c;
        sa_[j] = r * 128 + (((2 * c) ^ (r & 15)) << 3);
    }

    uint64_t acc[10];
    #pragma unroll
    for (int o = 0; o < 10; ++o) acc[o] = 0ull;

    // prefetch tile 0
    float4 px[7];
    #pragma unroll
    for (int j = 0; j < 7; ++j) px[j] = gp_[j][0];
    float pe0 = g_Epack[tid];
    float pe1 = g_Epack[tid + 128];
    float pe2 = (tid < 24) ? g_Epack[tid + 256] : 0.f;

    const int sw = (tid & 15);
    int buf = 0;

    for (int t = 0; t < NT; ++t) {
        // store staged tile into smem[buf]
        char* xb = (char*)Xs[buf];
        #pragma unroll
        for (int j = 0; j < 7; ++j) {
            *(float2*)(xb + sa_[j])       = make_float2(px[j].x, px[j].y);
            *(float2*)(xb + (sa_[j] ^ 8)) = make_float2(px[j].z, px[j].w);
        }
        Es[buf][tid]       = pe0;
        Es[buf][tid + 128] = pe1;
        if (tid < 24) Es[buf][tid + 256] = pe2;
        __syncthreads();

        // prefetch tile t+1 (latency overlapped with compute below)
        if (t + 1 < NT) {
            #pragma unroll
            for (int j = 0; j < 7; ++j) px[j] = gp_[j][(t + 1) * 7];
            const float* eb = g_Epack + (t + 1) * 280;
            pe0 = eb[tid];
            pe1 = eb[tid + 128];
            if (tid < 24) pe2 = eb[tid + 256];
        }

        // compute tile t: lane owns row = tid
        const char* bx = (const char*)Xs[buf] + tid * 128;
        #pragma unroll
        for (int kk = 0; kk < 14; ++kk) {
            const uint64_t x = *(const uint64_t*)(bx + (((kk ^ sw)) << 3));
            const ulonglong2* ep = (const ulonglong2*)&Es[buf][kk * 20];
            #pragma unroll
            for (int oo = 0; oo < 5; ++oo) {
                ulonglong2 e = ep[oo];
                fma2(acc[2 * oo],     x, e.x);
                fma2(acc[2 * oo + 1], x, e.y);
            }
        }
        buf ^= 1;
        // no second sync needed: a thread reaching the next store has passed
        // the sync above, which all threads reach only after finishing the
        // compute that read the buffer being overwritten.
    }

    // epilogue: reduce even/odd halves, add bias, store
    const int row = rowBlock + tid;
    #pragma unroll
    for (int o = 0; o < 10; ++o) {
        float lo, hi;
        asm("mov.b64 {%0,%1}, %2;" : "=f"(lo), "=f"(hi) : "l"(acc[o]));
        Y[row * 10 + o] = lo + hi + g_c[o];
    }
}

extern "C" void kernel_launch(void* const* d_in, const int* in_sizes, int n_in,
                              void* d_out, int out_size) {
    (void)in_sizes; (void)n_in; (void)out_size;
    FoldArgs fa;
    for (int i = 0; i < 9; ++i) {
        fa.W[i] = (const float*)d_in[1 + 2 * i];
        fa.b[i] = (const float*)d_in[2 + 2 * i];
    }
    fold_kernel<<<49, 256>>>(fa);
    gemm_kernel<<<512, 128>>>((const float*)d_in[0], (float*)d_out);
}